// round 2
// baseline (speedup 1.0000x reference)
#include <cuda_runtime.h>

#define FEAT 128
#define NMAX 8192
#define ROWS_PER_BLOCK 64

// Scratch (no allocations allowed in kernel_launch).
__device__ float g_deg[NMAX];
__device__ float g_dis[NMAX];
__device__ float g_scaled[(size_t)NMAX * FEAT];  // dis[j] * (x[j] @ W)

// ---------------------------------------------------------------------------
// K1: zero the degree accumulator (re-run every launch: graph replays).
// ---------------------------------------------------------------------------
__global__ void k_zero_deg(int n) {
    int i = blockIdx.x * blockDim.x + threadIdx.x;
    if (i < n) g_deg[i] = 0.0f;
}

// ---------------------------------------------------------------------------
// K2: degree = sum of edge weights per source row (self-loop +1 added later).
// adj is int32 (JAX demotes int64 without x64 mode).
// ---------------------------------------------------------------------------
__global__ void k_deg(const int* __restrict__ adj0,
                      const float* __restrict__ ew, int E) {
    int e = blockIdx.x * blockDim.x + threadIdx.x;
    if (e < E) atomicAdd(&g_deg[adj0[e]], ew[e]);
}

// ---------------------------------------------------------------------------
// K3: support = x @ W; scaled[r] = dis_r * support[r];
//     out[r] = bias + dis_r * scaled[r]  (self-loop term); dis cached.
// 256 threads, 64 rows/block. Warp w -> rows [8w, 8w+8), lane l -> cols
// [4l, 4l+4). W (64KB) + A-tile (32KB) in dynamic smem.
// ---------------------------------------------------------------------------
__global__ void k_gemm(const float* __restrict__ x,
                       const float* __restrict__ w,
                       const float* __restrict__ bias,
                       float* __restrict__ out, int n) {
    extern __shared__ float smem[];
    float* Ws = smem;                 // [128][128]
    float* As = smem + FEAT * FEAT;   // [64][128]

    int tid  = threadIdx.x;
    int lane = tid & 31;
    int warp = tid >> 5;
    int row0 = blockIdx.x * ROWS_PER_BLOCK;

    for (int idx = tid; idx < FEAT * FEAT / 4; idx += 256)
        ((float4*)Ws)[idx] = ((const float4*)w)[idx];
    const float4* xg = (const float4*)(x + (size_t)row0 * FEAT);
    for (int idx = tid; idx < ROWS_PER_BLOCK * FEAT / 4; idx += 256)
        ((float4*)As)[idx] = xg[idx];
    __syncthreads();

    float4 acc[8];
#pragma unroll
    for (int r = 0; r < 8; r++) acc[r] = make_float4(0.f, 0.f, 0.f, 0.f);

    const float* Arow = As + warp * 8 * FEAT;

#pragma unroll 2
    for (int k = 0; k < FEAT; k += 4) {
        float4 w0 = *(const float4*)&Ws[(k + 0) * FEAT + lane * 4];
        float4 w1 = *(const float4*)&Ws[(k + 1) * FEAT + lane * 4];
        float4 w2 = *(const float4*)&Ws[(k + 2) * FEAT + lane * 4];
        float4 w3 = *(const float4*)&Ws[(k + 3) * FEAT + lane * 4];
#pragma unroll
        for (int r = 0; r < 8; r++) {
            float4 av = *(const float4*)&Arow[r * FEAT + k];  // broadcast LDS.128
            acc[r].x += av.x * w0.x; acc[r].y += av.x * w0.y;
            acc[r].z += av.x * w0.z; acc[r].w += av.x * w0.w;
            acc[r].x += av.y * w1.x; acc[r].y += av.y * w1.y;
            acc[r].z += av.y * w1.z; acc[r].w += av.y * w1.w;
            acc[r].x += av.z * w2.x; acc[r].y += av.z * w2.y;
            acc[r].z += av.z * w2.z; acc[r].w += av.z * w2.w;
            acc[r].x += av.w * w3.x; acc[r].y += av.w * w3.y;
            acc[r].z += av.w * w3.z; acc[r].w += av.w * w3.w;
        }
    }

    float4 bv = ((const float4*)bias)[lane];
#pragma unroll
    for (int r = 0; r < 8; r++) {
        int row = row0 + warp * 8 + r;
        float dis = rsqrtf(g_deg[row] + 1.0f + 1e-10f);
        if (lane == 0) g_dis[row] = dis;
        float4 a = acc[r];
        float4 sc = make_float4(dis * a.x, dis * a.y, dis * a.z, dis * a.w);
        ((float4*)(g_scaled + (size_t)row * FEAT))[lane] = sc;
        float4 o = make_float4(bv.x + dis * sc.x, bv.y + dis * sc.y,
                               bv.z + dis * sc.z, bv.w + dis * sc.w);
        ((float4*)(out + (size_t)row * FEAT))[lane] = o;
    }
}

// ---------------------------------------------------------------------------
// K4: edge-parallel aggregation. One warp per edge; lane l handles cols
// [4l, 4l+4). out[i] += (dis_i * w_e) * scaled[j]  via red.global.add.v4.f32.
// g_scaled (4 MB) is L2-resident; row loads fully coalesced (512B).
// ---------------------------------------------------------------------------
__global__ void k_agg(const int* __restrict__ adj0,
                      const int* __restrict__ adj1,
                      const float* __restrict__ ew,
                      float* __restrict__ out, int E) {
    int g = blockIdx.x * blockDim.x + threadIdx.x;
    int e = g >> 5;
    int lane = g & 31;
    if (e >= E) return;
    int i = adj0[e];   // warp-uniform broadcast loads
    int j = adj1[e];
    float s = ew[e] * g_dis[i];
    float4 v = ((const float4*)(g_scaled + (size_t)j * FEAT))[lane];
    float4 r = make_float4(s * v.x, s * v.y, s * v.z, s * v.w);
    float* p = out + (size_t)i * FEAT + lane * 4;
    asm volatile("red.global.add.v4.f32 [%0], {%1,%2,%3,%4};"
                 :: "l"(p), "f"(r.x), "f"(r.y), "f"(r.z), "f"(r.w)
                 : "memory");
}

// ---------------------------------------------------------------------------
extern "C" void kernel_launch(void* const* d_in, const int* in_sizes, int n_in,
                              void* d_out, int out_size) {
    const float* x    = (const float*)d_in[0];
    const int*   adj  = (const int*)d_in[1];     // int32 [2, E]
    const float* ew   = (const float*)d_in[2];
    const float* w    = (const float*)d_in[3];
    const float* bias = (const float*)d_in[4];
    float*       out  = (float*)d_out;

    int n = in_sizes[0] / FEAT;     // 8192
    int E = in_sizes[2];            // 262144

    k_zero_deg<<<(n + 255) / 256, 256>>>(n);
    k_deg<<<(E + 255) / 256, 256>>>(adj, ew, E);

    cudaFuncSetAttribute(k_gemm, cudaFuncAttributeMaxDynamicSharedMemorySize,
                         (FEAT * FEAT + ROWS_PER_BLOCK * FEAT) * sizeof(float));
    k_gemm<<<n / ROWS_PER_BLOCK, 256,
             (FEAT * FEAT + ROWS_PER_BLOCK * FEAT) * sizeof(float)>>>(
        x, w, bias, out, n);

    long long total_threads = (long long)E * 32;
    int blocks = (int)((total_threads + 255) / 256);
    k_agg<<<blocks, 256>>>(adj, adj + E, ew, out, E);
}